// round 13
// baseline (speedup 1.0000x reference)
#include <cuda_runtime.h>
#include <cuda_fp16.h>

#define N_NODES 100000
#define N_EDGES 1600000
#define IN_DIM  128
#define OUT_DIM 64
#define NEG_SLOPE 0.2f

#define SCAN_B 1024
#define SCAN_NB ((N_NODES + SCAN_B - 1) / SCAN_B)   // 98
#define GEMM_BLOCKS ((N_NODES + 63) / 64)           // 1563
#define HIST_BLOCKS ((N_EDGES / 4 + 255) / 256)     // 1563

// Scratch (static device globals — zero-init at load; g_count self-cleaning)
__device__ __align__(16) __half g_Whh[(size_t)N_NODES * OUT_DIM];
__device__ float g_ssrc[N_NODES];
__device__ float g_sdst[N_NODES];
__device__ int   g_count[N_NODES];     // agg zeroes after use
__device__ int   g_rowstart[N_NODES];
__device__ int   g_bsum[SCAN_NB];
__device__ __align__(8) unsigned short g_eoff[N_EDGES];  // within-row rank (<= ~60)
__device__ int   g_ecol[N_EDGES];      // col indices grouped by row

// ---------------------------------------------------------------------------
// K1: role-split. GEMM blocks: Wh = h@W fused with s_src/s_dst.
// Hist blocks: row histogram + within-row rank (uint16), hidden under GEMM.
// ---------------------------------------------------------------------------
__global__ void gemm_hist_kernel(const float* __restrict__ h,
                                 const float* __restrict__ W,
                                 const float* __restrict__ a,
                                 const int*   __restrict__ row) {
    __shared__ __align__(16) float hs[64][68];
    __shared__ __align__(16) float Ws[64][64];

    const int tid = threadIdx.x;

    if (blockIdx.x >= GEMM_BLOCKS) {
        // ---- histogram + rank role: 4 edges per thread ----
        int t = (blockIdx.x - GEMM_BLOCKS) * blockDim.x + tid;
        int e4 = t * 4;
        if (e4 + 3 < N_EDGES) {
            int4 r = ((const int4*)row)[t];
            unsigned int o0 = (unsigned int)atomicAdd(&g_count[r.x], 1);
            unsigned int o1 = (unsigned int)atomicAdd(&g_count[r.y], 1);
            unsigned int o2 = (unsigned int)atomicAdd(&g_count[r.z], 1);
            unsigned int o3 = (unsigned int)atomicAdd(&g_count[r.w], 1);
            uint2 pk;
            pk.x = (o0 & 0xFFFFu) | (o1 << 16);
            pk.y = (o2 & 0xFFFFu) | (o3 << 16);
            ((uint2*)g_eoff)[t] = pk;            // 4 ushorts, 8B aligned
        } else {
            for (int e = e4; e < N_EDGES; e++)
                g_eoff[e] = (unsigned short)atomicAdd(&g_count[row[e]], 1);
        }
        return;
    }

    // ---- GEMM role ----
    const int tx   = tid & 15;
    const int ty   = tid >> 4;
    const int row0 = blockIdx.x * 64;

    float acc[4][4];
    #pragma unroll
    for (int i = 0; i < 4; i++)
        #pragma unroll
        for (int j = 0; j < 4; j++) acc[i][j] = 0.f;

    #pragma unroll
    for (int kc = 0; kc < 2; kc++) {
        #pragma unroll
        for (int p = 0; p < 4; p++) {
            int idx = tid + p * 256;
            int r = idx >> 4, c4 = idx & 15;
            int node = row0 + r;
            float4 v = make_float4(0.f, 0.f, 0.f, 0.f);
            if (node < N_NODES)
                v = ((const float4*)h)[(size_t)node * 32 + kc * 16 + c4];
            *(float4*)&hs[r][c4 * 4] = v;
        }
        #pragma unroll
        for (int p = 0; p < 4; p++) {
            int idx = tid + p * 256;
            int k = idx >> 4, n4 = idx & 15;
            *(float4*)&Ws[k][n4 * 4] =
                ((const float4*)W)[(size_t)(kc * 64 + k) * 16 + n4];
        }
        __syncthreads();

        #pragma unroll 8
        for (int k = 0; k < 64; k++) {
            float4 wv = *(const float4*)&Ws[k][tx * 4];
            float h0 = hs[ty * 4 + 0][k];
            float h1 = hs[ty * 4 + 1][k];
            float h2 = hs[ty * 4 + 2][k];
            float h3 = hs[ty * 4 + 3][k];
            acc[0][0] = fmaf(h0, wv.x, acc[0][0]);
            acc[0][1] = fmaf(h0, wv.y, acc[0][1]);
            acc[0][2] = fmaf(h0, wv.z, acc[0][2]);
            acc[0][3] = fmaf(h0, wv.w, acc[0][3]);
            acc[1][0] = fmaf(h1, wv.x, acc[1][0]);
            acc[1][1] = fmaf(h1, wv.y, acc[1][1]);
            acc[1][2] = fmaf(h1, wv.z, acc[1][2]);
            acc[1][3] = fmaf(h1, wv.w, acc[1][3]);
            acc[2][0] = fmaf(h2, wv.x, acc[2][0]);
            acc[2][1] = fmaf(h2, wv.y, acc[2][1]);
            acc[2][2] = fmaf(h2, wv.z, acc[2][2]);
            acc[2][3] = fmaf(h2, wv.w, acc[2][3]);
            acc[3][0] = fmaf(h3, wv.x, acc[3][0]);
            acc[3][1] = fmaf(h3, wv.y, acc[3][1]);
            acc[3][2] = fmaf(h3, wv.z, acc[3][2]);
            acc[3][3] = fmaf(h3, wv.w, acc[3][3]);
        }
        __syncthreads();
    }

    const float4 as = *(const float4*)&a[tx * 4];
    const float4 ad = *(const float4*)&a[64 + tx * 4];
    float ss[4], sd[4];
    #pragma unroll
    for (int i = 0; i < 4; i++) {
        int node = row0 + ty * 4 + i;
        if (node < N_NODES) {
            __half2 lo = __floats2half2_rn(acc[i][0], acc[i][1]);
            __half2 hi = __floats2half2_rn(acc[i][2], acc[i][3]);
            uint2 pk;
            pk.x = *(unsigned int*)&lo;
            pk.y = *(unsigned int*)&hi;
            ((uint2*)g_Whh)[(size_t)node * 16 + tx] = pk;
        }
        ss[i] = acc[i][0] * as.x + acc[i][1] * as.y + acc[i][2] * as.z + acc[i][3] * as.w;
        sd[i] = acc[i][0] * ad.x + acc[i][1] * ad.y + acc[i][2] * ad.z + acc[i][3] * ad.w;
    }
    #pragma unroll
    for (int o = 8; o > 0; o >>= 1) {
        #pragma unroll
        for (int i = 0; i < 4; i++) {
            ss[i] += __shfl_down_sync(0xFFFFFFFFu, ss[i], o, 16);
            sd[i] += __shfl_down_sync(0xFFFFFFFFu, sd[i], o, 16);
        }
    }
    if (tx == 0) {
        #pragma unroll
        for (int i = 0; i < 4; i++) {
            int node = row0 + ty * 4 + i;
            if (node < N_NODES) { g_ssrc[node] = ss[i]; g_sdst[node] = sd[i]; }
        }
    }
}

// ---------------------------------------------------------------------------
// K2: block-local exclusive scan of g_count -> g_rowstart, block sums in bsum
// ---------------------------------------------------------------------------
__global__ void scan1_kernel() {
    __shared__ int s[SCAN_B];
    int i = blockIdx.x * SCAN_B + threadIdx.x;
    int v = (i < N_NODES) ? g_count[i] : 0;
    s[threadIdx.x] = v;
    __syncthreads();
    int x = v;
    #pragma unroll
    for (int o = 1; o < SCAN_B; o <<= 1) {
        int t = (threadIdx.x >= o) ? s[threadIdx.x - o] : 0;
        __syncthreads();
        x += t;
        s[threadIdx.x] = x;
        __syncthreads();
    }
    if (i < N_NODES) g_rowstart[i] = x - v;
    if (threadIdx.x == SCAN_B - 1) g_bsum[blockIdx.x] = x;
}

// ---------------------------------------------------------------------------
// K3: add bsum prefix to rowstart
// ---------------------------------------------------------------------------
__global__ void scan3_kernel() {
    __shared__ int warp_part[4];
    __shared__ int s_prefix;
    const int b = blockIdx.x;
    const int t = threadIdx.x;

    if (t < 128) {
        int v = (t < b) ? g_bsum[t] : 0;     // b <= 97 < 128
        #pragma unroll
        for (int o = 16; o > 0; o >>= 1)
            v += __shfl_down_sync(0xFFFFFFFFu, v, o);
        if ((t & 31) == 0) warp_part[t >> 5] = v;
    }
    __syncthreads();
    if (t == 0)
        s_prefix = warp_part[0] + warp_part[1] + warp_part[2] + warp_part[3];
    __syncthreads();

    int i = b * SCAN_B + t;
    if (i < N_NODES)
        g_rowstart[i] += s_prefix;
}

// ---------------------------------------------------------------------------
// K4: atomic-free scatter: ecol[rowstart[r] + eoff[e]] = c. 8 edges/thread.
// One L2-resident gather (rowstart) + one random 4B store per edge; all
// loads independent -> deep MLP, unlike the atomic-return chain.
// ---------------------------------------------------------------------------
__global__ void scatter_kernel(const int* __restrict__ row,
                               const int* __restrict__ col) {
    int t = blockIdx.x * blockDim.x + threadIdx.x;
    int e8 = t * 8;
    if (e8 + 7 < N_EDGES) {
        int4 r0 = ((const int4*)row)[2 * t];
        int4 r1 = ((const int4*)row)[2 * t + 1];
        int4 c0 = ((const int4*)col)[2 * t];
        int4 c1 = ((const int4*)col)[2 * t + 1];
        uint2 ePk0 = ((const uint2*)g_eoff)[2 * t];
        uint2 ePk1 = ((const uint2*)g_eoff)[2 * t + 1];
        int rr[8] = {r0.x, r0.y, r0.z, r0.w, r1.x, r1.y, r1.z, r1.w};
        int cc[8] = {c0.x, c0.y, c0.z, c0.w, c1.x, c1.y, c1.z, c1.w};
        int oo[8] = {(int)(ePk0.x & 0xFFFFu), (int)(ePk0.x >> 16),
                     (int)(ePk0.y & 0xFFFFu), (int)(ePk0.y >> 16),
                     (int)(ePk1.x & 0xFFFFu), (int)(ePk1.x >> 16),
                     (int)(ePk1.y & 0xFFFFu), (int)(ePk1.y >> 16)};
        int st[8];
        #pragma unroll
        for (int j = 0; j < 8; j++) st[j] = __ldg(&g_rowstart[rr[j]]);
        #pragma unroll
        for (int j = 0; j < 8; j++) g_ecol[st[j] + oo[j]] = cc[j];
    } else {
        for (int e = e8; e < N_EDGES; e++)
            g_ecol[g_rowstart[row[e]] + (int)g_eoff[e]] = col[e];
    }
}

// ---------------------------------------------------------------------------
// K5: single-pass per-node aggregation. ssrc[row] warp-uniform; lanes compute
// weights from sdst[col]; broadcast loop over fp16 Wh gathers; normalize at end.
// ---------------------------------------------------------------------------
__global__ void agg_csr_kernel(float* __restrict__ out) {
    const int warp = (blockIdx.x * blockDim.x + threadIdx.x) >> 5;
    const int lane = threadIdx.x & 31;
    if (warp >= N_NODES) return;

    const int start = g_rowstart[warp];
    const int cnt   = g_count[warp];
    const float ssr = g_ssrc[warp];

    const int half = lane >> 4;
    const int hl   = lane & 15;

    const uint2* Wh4 = (const uint2*)g_Whh;
    float4 acc = make_float4(0.f, 0.f, 0.f, 0.f);
    float dsum = 0.f;

    for (int base = 0; base < cnt; base += 32) {
        int idx = base + lane;
        int c_lane = 0;
        float w_lane = 0.f;
        if (idx < cnt) {
            c_lane = __ldg(&g_ecol[start + idx]);
            float x = ssr + __ldg(&g_sdst[c_lane]);
            x = (x > 0.f) ? x : NEG_SLOPE * x;
            w_lane = __expf(x);
        }
        dsum += w_lane;
        int m = cnt - base; if (m > 32) m = 32;
        int nsteps = (m + 1) >> 1;
        #pragma unroll 4
        for (int j = 0; j < nsteps; j++) {
            int src = 2 * j + half;
            int   c = __shfl_sync(0xFFFFFFFFu, c_lane, src);
            float w = __shfl_sync(0xFFFFFFFFu, w_lane, src);
            uint2 raw = __ldg(&Wh4[(size_t)c * 16 + hl]);
            float2 v0 = __half22float2(*(const __half2*)&raw.x);
            float2 v1 = __half22float2(*(const __half2*)&raw.y);
            acc.x = fmaf(w, v0.x, acc.x);
            acc.y = fmaf(w, v0.y, acc.y);
            acc.z = fmaf(w, v1.x, acc.z);
            acc.w = fmaf(w, v1.y, acc.w);
        }
    }

    #pragma unroll
    for (int o = 16; o > 0; o >>= 1)
        dsum += __shfl_xor_sync(0xFFFFFFFFu, dsum, o);
    const float inv = 1.f / (dsum + 1e-10f);

    acc.x += __shfl_xor_sync(0xFFFFFFFFu, acc.x, 16);
    acc.y += __shfl_xor_sync(0xFFFFFFFFu, acc.y, 16);
    acc.z += __shfl_xor_sync(0xFFFFFFFFu, acc.z, 16);
    acc.w += __shfl_xor_sync(0xFFFFFFFFu, acc.w, 16);

    if (half == 0) {
        acc.x *= inv; acc.y *= inv; acc.z *= inv; acc.w *= inv;
        ((float4*)out)[(size_t)warp * 16 + hl] = acc;
    }

    if (lane == 0) g_count[warp] = 0;   // self-clean for next replay
}

// ---------------------------------------------------------------------------
extern "C" void kernel_launch(void* const* d_in, const int* in_sizes, int n_in,
                              void* d_out, int out_size) {
    const float* h   = (const float*)d_in[0];
    const int*   row = (const int*)d_in[1];
    const int*   col = (const int*)d_in[2];
    const float* W   = (const float*)d_in[3];
    const float* a   = (const float*)d_in[4];
    float*       out = (float*)d_out;

    gemm_hist_kernel<<<GEMM_BLOCKS + HIST_BLOCKS, 256>>>(h, W, a, row);
    scan1_kernel<<<SCAN_NB, SCAN_B>>>();
    scan3_kernel<<<SCAN_NB, SCAN_B>>>();
    scatter_kernel<<<(N_EDGES / 8 + 255) / 256, 256>>>(row, col);
    agg_csr_kernel<<<(N_NODES * 32 + 255) / 256, 256>>>(out);
}

// round 14
// speedup vs baseline: 1.0136x; 1.0136x over previous
#include <cuda_runtime.h>
#include <cuda_fp16.h>

#define N_NODES 100000
#define N_EDGES 1600000
#define IN_DIM  128
#define OUT_DIM 64
#define NEG_SLOPE 0.2f

#define SCAN_B 1024
#define SCAN_NB ((N_NODES + SCAN_B - 1) / SCAN_B)   // 98
#define GEMM_BLOCKS ((N_NODES + 63) / 64)           // 1563
#define HIST_BLOCKS ((N_EDGES / 4 + 255) / 256)     // 1563

// Scratch (static device globals — zero-init at load; g_count self-cleaning)
__device__ __align__(16) __half g_Whh[(size_t)N_NODES * OUT_DIM];
__device__ float g_ssrc[N_NODES];
__device__ float g_sdst[N_NODES];
__device__ int   g_count[N_NODES];     // agg zeroes after use
__device__ int   g_rowstart[N_NODES];
__device__ int   g_bsum[SCAN_NB];
__device__ __align__(8) unsigned short g_eoff[N_EDGES];  // within-row rank
__device__ int   g_ecol[N_EDGES];      // col indices grouped by row

// ---------------------------------------------------------------------------
// K1: role-split, INTERLEAVED by block parity so every wave mixes FMA-bound
// GEMM blocks with L2-atomic-bound hist blocks (true overlap).
// ---------------------------------------------------------------------------
__global__ void gemm_hist_kernel(const float* __restrict__ h,
                                 const float* __restrict__ W,
                                 const float* __restrict__ a,
                                 const int*   __restrict__ row) {
    __shared__ __align__(16) float hs[64][68];
    __shared__ __align__(16) float Ws[64][64];

    const int tid = threadIdx.x;

    if (blockIdx.x & 1) {
        // ---- histogram + rank role: 4 edges per thread ----
        int t = (blockIdx.x >> 1) * blockDim.x + tid;
        int e4 = t * 4;
        if (e4 < N_EDGES) {      // N_EDGES % 4 == 0 -> full int4 when in range
            int4 r = ((const int4*)row)[t];
            unsigned int o0 = (unsigned int)atomicAdd(&g_count[r.x], 1);
            unsigned int o1 = (unsigned int)atomicAdd(&g_count[r.y], 1);
            unsigned int o2 = (unsigned int)atomicAdd(&g_count[r.z], 1);
            unsigned int o3 = (unsigned int)atomicAdd(&g_count[r.w], 1);
            uint2 pk;
            pk.x = (o0 & 0xFFFFu) | (o1 << 16);
            pk.y = (o2 & 0xFFFFu) | (o3 << 16);
            ((uint2*)g_eoff)[t] = pk;
        }
        return;
    }

    // ---- GEMM role ----
    const int tx   = tid & 15;
    const int ty   = tid >> 4;
    const int row0 = (blockIdx.x >> 1) * 64;

    float acc[4][4];
    #pragma unroll
    for (int i = 0; i < 4; i++)
        #pragma unroll
        for (int j = 0; j < 4; j++) acc[i][j] = 0.f;

    #pragma unroll
    for (int kc = 0; kc < 2; kc++) {
        #pragma unroll
        for (int p = 0; p < 4; p++) {
            int idx = tid + p * 256;
            int r = idx >> 4, c4 = idx & 15;
            int node = row0 + r;
            float4 v = make_float4(0.f, 0.f, 0.f, 0.f);
            if (node < N_NODES)
                v = ((const float4*)h)[(size_t)node * 32 + kc * 16 + c4];
            *(float4*)&hs[r][c4 * 4] = v;
        }
        #pragma unroll
        for (int p = 0; p < 4; p++) {
            int idx = tid + p * 256;
            int k = idx >> 4, n4 = idx & 15;
            *(float4*)&Ws[k][n4 * 4] =
                ((const float4*)W)[(size_t)(kc * 64 + k) * 16 + n4];
        }
        __syncthreads();

        #pragma unroll 8
        for (int k = 0; k < 64; k++) {
            float4 wv = *(const float4*)&Ws[k][tx * 4];
            float h0 = hs[ty * 4 + 0][k];
            float h1 = hs[ty * 4 + 1][k];
            float h2 = hs[ty * 4 + 2][k];
            float h3 = hs[ty * 4 + 3][k];
            acc[0][0] = fmaf(h0, wv.x, acc[0][0]);
            acc[0][1] = fmaf(h0, wv.y, acc[0][1]);
            acc[0][2] = fmaf(h0, wv.z, acc[0][2]);
            acc[0][3] = fmaf(h0, wv.w, acc[0][3]);
            acc[1][0] = fmaf(h1, wv.x, acc[1][0]);
            acc[1][1] = fmaf(h1, wv.y, acc[1][1]);
            acc[1][2] = fmaf(h1, wv.z, acc[1][2]);
            acc[1][3] = fmaf(h1, wv.w, acc[1][3]);
            acc[2][0] = fmaf(h2, wv.x, acc[2][0]);
            acc[2][1] = fmaf(h2, wv.y, acc[2][1]);
            acc[2][2] = fmaf(h2, wv.z, acc[2][2]);
            acc[2][3] = fmaf(h2, wv.w, acc[2][3]);
            acc[3][0] = fmaf(h3, wv.x, acc[3][0]);
            acc[3][1] = fmaf(h3, wv.y, acc[3][1]);
            acc[3][2] = fmaf(h3, wv.z, acc[3][2]);
            acc[3][3] = fmaf(h3, wv.w, acc[3][3]);
        }
        __syncthreads();
    }

    const float4 as = *(const float4*)&a[tx * 4];
    const float4 ad = *(const float4*)&a[64 + tx * 4];
    float ss[4], sd[4];
    #pragma unroll
    for (int i = 0; i < 4; i++) {
        int node = row0 + ty * 4 + i;
        if (node < N_NODES) {
            __half2 lo = __floats2half2_rn(acc[i][0], acc[i][1]);
            __half2 hi = __floats2half2_rn(acc[i][2], acc[i][3]);
            uint2 pk;
            pk.x = *(unsigned int*)&lo;
            pk.y = *(unsigned int*)&hi;
            ((uint2*)g_Whh)[(size_t)node * 16 + tx] = pk;
        }
        ss[i] = acc[i][0] * as.x + acc[i][1] * as.y + acc[i][2] * as.z + acc[i][3] * as.w;
        sd[i] = acc[i][0] * ad.x + acc[i][1] * ad.y + acc[i][2] * ad.z + acc[i][3] * ad.w;
    }
    #pragma unroll
    for (int o = 8; o > 0; o >>= 1) {
        #pragma unroll
        for (int i = 0; i < 4; i++) {
            ss[i] += __shfl_down_sync(0xFFFFFFFFu, ss[i], o, 16);
            sd[i] += __shfl_down_sync(0xFFFFFFFFu, sd[i], o, 16);
        }
    }
    if (tx == 0) {
        #pragma unroll
        for (int i = 0; i < 4; i++) {
            int node = row0 + ty * 4 + i;
            if (node < N_NODES) { g_ssrc[node] = ss[i]; g_sdst[node] = sd[i]; }
        }
    }
}

// ---------------------------------------------------------------------------
// K2: block-local exclusive scan of g_count -> g_rowstart, block sums in bsum
// ---------------------------------------------------------------------------
__global__ void scan1_kernel() {
    __shared__ int s[SCAN_B];
    int i = blockIdx.x * SCAN_B + threadIdx.x;
    int v = (i < N_NODES) ? g_count[i] : 0;
    s[threadIdx.x] = v;
    __syncthreads();
    int x = v;
    #pragma unroll
    for (int o = 1; o < SCAN_B; o <<= 1) {
        int t = (threadIdx.x >= o) ? s[threadIdx.x - o] : 0;
        __syncthreads();
        x += t;
        s[threadIdx.x] = x;
        __syncthreads();
    }
    if (i < N_NODES) g_rowstart[i] = x - v;
    if (threadIdx.x == SCAN_B - 1) g_bsum[blockIdx.x] = x;
}

// ---------------------------------------------------------------------------
// K3: add bsum prefix to rowstart
// ---------------------------------------------------------------------------
__global__ void scan3_kernel() {
    __shared__ int warp_part[4];
    __shared__ int s_prefix;
    const int b = blockIdx.x;
    const int t = threadIdx.x;

    if (t < 128) {
        int v = (t < b) ? g_bsum[t] : 0;     // b <= 97 < 128
        #pragma unroll
        for (int o = 16; o > 0; o >>= 1)
            v += __shfl_down_sync(0xFFFFFFFFu, v, o);
        if ((t & 31) == 0) warp_part[t >> 5] = v;
    }
    __syncthreads();
    if (t == 0)
        s_prefix = warp_part[0] + warp_part[1] + warp_part[2] + warp_part[3];
    __syncthreads();

    int i = b * SCAN_B + t;
    if (i < N_NODES)
        g_rowstart[i] += s_prefix;
}

// ---------------------------------------------------------------------------
// K4: atomic-free scatter: ecol[rowstart[r] + eoff[e]] = c. 4 edges/thread
// (doubled thread count vs R13 for more outstanding-miss parallelism).
// ---------------------------------------------------------------------------
__global__ void scatter_kernel(const int* __restrict__ row,
                               const int* __restrict__ col) {
    int t = blockIdx.x * blockDim.x + threadIdx.x;
    int e4 = t * 4;
    if (e4 >= N_EDGES) return;       // N_EDGES % 4 == 0 -> full int4 in range
    int4 r = ((const int4*)row)[t];
    int4 c = ((const int4*)col)[t];
    uint2 ePk = ((const uint2*)g_eoff)[t];
    int rr[4] = {r.x, r.y, r.z, r.w};
    int cc[4] = {c.x, c.y, c.z, c.w};
    int oo[4] = {(int)(ePk.x & 0xFFFFu), (int)(ePk.x >> 16),
                 (int)(ePk.y & 0xFFFFu), (int)(ePk.y >> 16)};
    int st[4];
    #pragma unroll
    for (int j = 0; j < 4; j++) st[j] = __ldg(&g_rowstart[rr[j]]);
    #pragma unroll
    for (int j = 0; j < 4; j++) g_ecol[st[j] + oo[j]] = cc[j];
}

// ---------------------------------------------------------------------------
// K5: single-pass per-node aggregation. ssrc[row] warp-uniform; lanes compute
// weights from sdst[col]; broadcast loop over fp16 Wh gathers; normalize at end.
// ---------------------------------------------------------------------------
__global__ void agg_csr_kernel(float* __restrict__ out) {
    const int warp = (blockIdx.x * blockDim.x + threadIdx.x) >> 5;
    const int lane = threadIdx.x & 31;
    if (warp >= N_NODES) return;

    const int start = g_rowstart[warp];
    const int cnt   = g_count[warp];
    const float ssr = g_ssrc[warp];

    const int half = lane >> 4;
    const int hl   = lane & 15;

    const uint2* Wh4 = (const uint2*)g_Whh;
    float4 acc = make_float4(0.f, 0.f, 0.f, 0.f);
    float dsum = 0.f;

    for (int base = 0; base < cnt; base += 32) {
        int idx = base + lane;
        int c_lane = 0;
        float w_lane = 0.f;
        if (idx < cnt) {
            c_lane = __ldg(&g_ecol[start + idx]);
            float x = ssr + __ldg(&g_sdst[c_lane]);
            x = (x > 0.f) ? x : NEG_SLOPE * x;
            w_lane = __expf(x);
        }
        dsum += w_lane;
        int m = cnt - base; if (m > 32) m = 32;
        int nsteps = (m + 1) >> 1;
        #pragma unroll 4
        for (int j = 0; j < nsteps; j++) {
            int src = 2 * j + half;
            int   c = __shfl_sync(0xFFFFFFFFu, c_lane, src);
            float w = __shfl_sync(0xFFFFFFFFu, w_lane, src);
            uint2 raw = __ldg(&Wh4[(size_t)c * 16 + hl]);
            float2 v0 = __half22float2(*(const __half2*)&raw.x);
            float2 v1 = __half22float2(*(const __half2*)&raw.y);
            acc.x = fmaf(w, v0.x, acc.x);
            acc.y = fmaf(w, v0.y, acc.y);
            acc.z = fmaf(w, v1.x, acc.z);
            acc.w = fmaf(w, v1.y, acc.w);
        }
    }

    #pragma unroll
    for (int o = 16; o > 0; o >>= 1)
        dsum += __shfl_xor_sync(0xFFFFFFFFu, dsum, o);
    const float inv = 1.f / (dsum + 1e-10f);

    acc.x += __shfl_xor_sync(0xFFFFFFFFu, acc.x, 16);
    acc.y += __shfl_xor_sync(0xFFFFFFFFu, acc.y, 16);
    acc.z += __shfl_xor_sync(0xFFFFFFFFu, acc.z, 16);
    acc.w += __shfl_xor_sync(0xFFFFFFFFu, acc.w, 16);

    if (half == 0) {
        acc.x *= inv; acc.y *= inv; acc.z *= inv; acc.w *= inv;
        ((float4*)out)[(size_t)warp * 16 + hl] = acc;
    }

    if (lane == 0) g_count[warp] = 0;   // self-clean for next replay
}

// ---------------------------------------------------------------------------
extern "C" void kernel_launch(void* const* d_in, const int* in_sizes, int n_in,
                              void* d_out, int out_size) {
    const float* h   = (const float*)d_in[0];
    const int*   row = (const int*)d_in[1];
    const int*   col = (const int*)d_in[2];
    const float* W   = (const float*)d_in[3];
    const float* a   = (const float*)d_in[4];
    float*       out = (float*)d_out;

    gemm_hist_kernel<<<GEMM_BLOCKS + HIST_BLOCKS, 256>>>(h, W, a, row);
    scan1_kernel<<<SCAN_NB, SCAN_B>>>();
    scan3_kernel<<<SCAN_NB, SCAN_B>>>();
    scatter_kernel<<<(N_EDGES / 4 + 255) / 256, 256>>>(row, col);
    agg_csr_kernel<<<(N_NODES * 32 + 255) / 256, 256>>>(out);
}

// round 15
// speedup vs baseline: 1.0323x; 1.0184x over previous
#include <cuda_runtime.h>
#include <cuda_fp16.h>

#define N_NODES 100000
#define N_EDGES 1600000
#define IN_DIM  128
#define OUT_DIM 64
#define NEG_SLOPE 0.2f

#define SCAN_B 1024
#define SCAN_NB ((N_NODES + SCAN_B - 1) / SCAN_B)   // 98
#define GEMM_BLOCKS ((N_NODES + 127) / 128)         // 782
#define HIST_BLOCKS ((N_EDGES / 4 + 255) / 256)     // 1563
#define TOTAL_BLOCKS (GEMM_BLOCKS * 3)              // 2346 (1:2 interleave)

// Scratch (static device globals — zero-init at load; g_count self-cleaning)
__device__ __align__(16) __half g_Whh[(size_t)N_NODES * OUT_DIM];
__device__ float g_ssrc[N_NODES];
__device__ float g_sdst[N_NODES];
__device__ int   g_count[N_NODES];     // agg zeroes after use
__device__ int   g_rowstart[N_NODES];
__device__ int   g_bsum[SCAN_NB];
__device__ __align__(8) unsigned short g_eoff[N_EDGES];  // within-row rank
__device__ int   g_ecol[N_EDGES];      // col indices grouped by row

// ---------------------------------------------------------------------------
// mma.sync m16n8k16 f16f16f32 (row.col). Standard sm_80+ fragment layout.
// ---------------------------------------------------------------------------
__device__ __forceinline__ void mma16816(float& d0, float& d1, float& d2, float& d3,
                                         unsigned a0, unsigned a1, unsigned a2, unsigned a3,
                                         unsigned b0, unsigned b1) {
    asm volatile(
        "mma.sync.aligned.m16n8k16.row.col.f32.f16.f16.f32 "
        "{%0,%1,%2,%3}, {%4,%5,%6,%7}, {%8,%9}, {%0,%1,%2,%3};"
        : "+f"(d0), "+f"(d1), "+f"(d2), "+f"(d3)
        : "r"(a0), "r"(a1), "r"(a2), "r"(a3), "r"(b0), "r"(b1));
}

// ---------------------------------------------------------------------------
// K1: role-split (1 GEMM : 2 hist interleave). GEMM: tensor-core Wh = h@W,
// 128 rows x 64 cols per block, fp16 inputs / f32 accum; f32 scores via
// s = h @ (W@a) computed from the f32 h tiles during load.
// ---------------------------------------------------------------------------
__global__ void gemm_hist_kernel(const float* __restrict__ h,
                                 const float* __restrict__ W,
                                 const float* __restrict__ a,
                                 const int*   __restrict__ row) {
    const int tid = threadIdx.x;
    const int mod = blockIdx.x % 3;

    if (mod != 0) {
        // ---- histogram + rank role: 4 edges per thread ----
        int hb = (blockIdx.x / 3) * 2 + (mod - 1);
        if (hb >= HIST_BLOCKS) return;
        int t = hb * blockDim.x + tid;
        if (t * 4 < N_EDGES) {
            int4 r = ((const int4*)row)[t];
            unsigned int o0 = (unsigned int)atomicAdd(&g_count[r.x], 1);
            unsigned int o1 = (unsigned int)atomicAdd(&g_count[r.y], 1);
            unsigned int o2 = (unsigned int)atomicAdd(&g_count[r.z], 1);
            unsigned int o3 = (unsigned int)atomicAdd(&g_count[r.w], 1);
            uint2 pk;
            pk.x = (o0 & 0xFFFFu) | (o1 << 16);
            pk.y = (o2 & 0xFFFFu) | (o3 << 16);
            ((uint2*)g_eoff)[t] = pk;
        }
        return;
    }

    // ---- GEMM role ----
    __shared__ __align__(16) __half hs[128][72];   // h chunk fp16 (stride 72 halfs)
    __shared__ __align__(16) __half Ws[64][72];    // W^T chunk fp16 [n][k]
    __shared__ float u_src[128], u_dst[128];
    __shared__ float a_sh[128];

    const int g    = blockIdx.x / 3;
    const int row0 = g * 128;
    const int lane = tid & 31;
    const int wrp  = tid >> 5;

    if (tid < 128) a_sh[tid] = a[tid];
    __syncthreads();

    // u = W @ a_src / a_dst  (f32, per block; W is L2-hot 32KB)
    if (tid < 128) {
        float us = 0.f, ud = 0.f;
        const float4* W4 = (const float4*)W;
        #pragma unroll 16
        for (int i = 0; i < 16; i++) {
            float4 w4 = W4[tid * 16 + i];
            us += w4.x * a_sh[i*4+0] + w4.y * a_sh[i*4+1]
                + w4.z * a_sh[i*4+2] + w4.w * a_sh[i*4+3];
            ud += w4.x * a_sh[64+i*4+0] + w4.y * a_sh[64+i*4+1]
                + w4.z * a_sh[64+i*4+2] + w4.w * a_sh[64+i*4+3];
        }
        u_src[tid] = us; u_dst[tid] = ud;
    }
    __syncthreads();

    float acc[8][4];
    #pragma unroll
    for (int nt = 0; nt < 8; nt++)
        #pragma unroll
        for (int j = 0; j < 4; j++) acc[nt][j] = 0.f;

    // score partials: thread covers row r = tid>>1, cols 32*(tid&1)..+31 per chunk
    const int srow = tid >> 1;
    const int scb  = (tid & 1) * 8;       // float4 base within chunk
    float ssp = 0.f, sdp = 0.f;

    const int r0 = wrp * 16 + (lane >> 2);
    const int k0 = (lane & 3) * 2;

    #pragma unroll
    for (int kc = 0; kc < 2; kc++) {
        // load h chunk (f32), convert to fp16, accumulate score partials
        {
            int node = row0 + srow;
            #pragma unroll
            for (int p = 0; p < 8; p++) {
                float4 v = make_float4(0.f, 0.f, 0.f, 0.f);
                if (node < N_NODES)
                    v = ((const float4*)h)[(size_t)node * 32 + kc * 16 + scb + p];
                int colb = (scb + p) * 4;
                *(__half2*)&hs[srow][colb]     = __floats2half2_rn(v.x, v.y);
                *(__half2*)&hs[srow][colb + 2] = __floats2half2_rn(v.z, v.w);
                int ub = kc * 64 + colb;
                ssp += v.x * u_src[ub] + v.y * u_src[ub+1] + v.z * u_src[ub+2] + v.w * u_src[ub+3];
                sdp += v.x * u_dst[ub] + v.y * u_dst[ub+1] + v.z * u_dst[ub+2] + v.w * u_dst[ub+3];
            }
        }
        // load W chunk transposed: Ws[n][k]
        #pragma unroll
        for (int p = 0; p < 4; p++) {
            int idx = tid + p * 256;          // < 1024
            int k = idx >> 4, n4 = idx & 15;
            float4 wv = ((const float4*)W)[(size_t)(kc * 64 + k) * 16 + n4];
            Ws[n4*4+0][k] = __float2half(wv.x);
            Ws[n4*4+1][k] = __float2half(wv.y);
            Ws[n4*4+2][k] = __float2half(wv.z);
            Ws[n4*4+3][k] = __float2half(wv.w);
        }
        __syncthreads();

        // 4 k16 steps of mma over this 64-wide chunk
        #pragma unroll
        for (int ks = 0; ks < 4; ks++) {
            int kb = ks * 16;
            unsigned a0 = *(const unsigned*)&hs[r0    ][kb + k0];
            unsigned a1 = *(const unsigned*)&hs[r0 + 8][kb + k0];
            unsigned a2 = *(const unsigned*)&hs[r0    ][kb + k0 + 8];
            unsigned a3 = *(const unsigned*)&hs[r0 + 8][kb + k0 + 8];
            #pragma unroll
            for (int nt = 0; nt < 8; nt++) {
                int n = nt * 8 + (lane >> 2);
                unsigned b0 = *(const unsigned*)&Ws[n][kb + k0];
                unsigned b1 = *(const unsigned*)&Ws[n][kb + k0 + 8];
                mma16816(acc[nt][0], acc[nt][1], acc[nt][2], acc[nt][3],
                         a0, a1, a2, a3, b0, b1);
            }
        }
        __syncthreads();
    }

    // scores: combine thread pairs (t even + t odd cover the full row)
    {
        float ss = ssp + __shfl_down_sync(0xFFFFFFFFu, ssp, 1);
        float sd = sdp + __shfl_down_sync(0xFFFFFFFFu, sdp, 1);
        int node = row0 + srow;
        if ((tid & 1) == 0 && node < N_NODES) {
            g_ssrc[node] = ss;
            g_sdst[node] = sd;
        }
    }

    // epilogue: write Wh as fp16 (d0,d1 = adjacent cols -> one half2 store)
    {
        int colb = (lane & 3) * 2;
        int ra = row0 + r0;        // rows r0 and r0+8
        #pragma unroll
        for (int nt = 0; nt < 8; nt++) {
            int c = nt * 8 + colb;
            if (ra < N_NODES)
                *(__half2*)&g_Whh[(size_t)ra * 64 + c] =
                    __floats2half2_rn(acc[nt][0], acc[nt][1]);
            if (ra + 8 < N_NODES)
                *(__half2*)&g_Whh[(size_t)(ra + 8) * 64 + c] =
                    __floats2half2_rn(acc[nt][2], acc[nt][3]);
        }
    }
}

// ---------------------------------------------------------------------------
// K2: block-local exclusive scan of g_count -> g_rowstart, block sums in bsum
// ---------------------------------------------------------------------------
__global__ void scan1_kernel() {
    __shared__ int s[SCAN_B];
    int i = blockIdx.x * SCAN_B + threadIdx.x;
    int v = (i < N_NODES) ? g_count[i] : 0;
    s[threadIdx.x] = v;
    __syncthreads();
    int x = v;
    #pragma unroll
    for (int o = 1; o < SCAN_B; o <<= 1) {
        int t = (threadIdx.x >= o) ? s[threadIdx.x - o] : 0;
        __syncthreads();
        x += t;
        s[threadIdx.x] = x;
        __syncthreads();
    }
    if (i < N_NODES) g_rowstart[i] = x - v;
    if (threadIdx.x == SCAN_B - 1) g_bsum[blockIdx.x] = x;
}

// ---------------------------------------------------------------------------
// K3: add bsum prefix to rowstart
// ---------------------------------------------------------------------------
__global__ void scan3_kernel() {
    __shared__ int warp_part[4];
    __shared__ int s_prefix;
    const int b = blockIdx.x;
    const int t = threadIdx.x;

    if (t < 128) {
        int v = (t < b) ? g_bsum[t] : 0;     // b <= 97 < 128
        #pragma unroll
        for (int o = 16; o > 0; o >>= 1)
            v += __shfl_down_sync(0xFFFFFFFFu, v, o);
        if ((t & 31) == 0) warp_part[t >> 5] = v;
    }
    __syncthreads();
    if (t == 0)
        s_prefix = warp_part[0] + warp_part[1] + warp_part[2] + warp_part[3];
    __syncthreads();

    int i = b * SCAN_B + t;
    if (i < N_NODES)
        g_rowstart[i] += s_prefix;
}

// ---------------------------------------------------------------------------
// K4: atomic-free scatter: ecol[rowstart[r] + eoff[e]] = c. 4 edges/thread.
// ---------------------------------------------------------------------------
__global__ void scatter_kernel(const int* __restrict__ row,
                               const int* __restrict__ col) {
    int t = blockIdx.x * blockDim.x + threadIdx.x;
    if (t * 4 >= N_EDGES) return;
    int4 r = ((const int4*)row)[t];
    int4 c = ((const int4*)col)[t];
    uint2 ePk = ((const uint2*)g_eoff)[t];
    int rr[4] = {r.x, r.y, r.z, r.w};
    int cc[4] = {c.x, c.y, c.z, c.w};
    int oo[4] = {(int)(ePk.x & 0xFFFFu), (int)(ePk.x >> 16),
                 (int)(ePk.y & 0xFFFFu), (int)(ePk.y >> 16)};
    int st[4];
    #pragma unroll
    for (int j = 0; j < 4; j++) st[j] = __ldg(&g_rowstart[rr[j]]);
    #pragma unroll
    for (int j = 0; j < 4; j++) g_ecol[st[j] + oo[j]] = cc[j];
}

// ---------------------------------------------------------------------------
// K5: single-pass per-node aggregation (unchanged from R14).
// ---------------------------------------------------------------------------
__global__ void agg_csr_kernel(float* __restrict__ out) {
    const int warp = (blockIdx.x * blockDim.x + threadIdx.x) >> 5;
    const int lane = threadIdx.x & 31;
    if (warp >= N_NODES) return;

    const int start = g_rowstart[warp];
    const int cnt   = g_count[warp];
    const float ssr = g_ssrc[warp];

    const int half = lane >> 4;
    const int hl   = lane & 15;

    const uint2* Wh4 = (const uint2*)g_Whh;
    float4 acc = make_float4(0.f, 0.f, 0.f, 0.f);
    float dsum = 0.f;

    for (int base = 0; base < cnt; base += 32) {
        int idx = base + lane;
        int c_lane = 0;
        float w_lane = 0.f;
        if (idx < cnt) {
            c_lane = __ldg(&g_ecol[start + idx]);
            float x = ssr + __ldg(&g_sdst[c_lane]);
            x = (x > 0.f) ? x : NEG_SLOPE * x;
            w_lane = __expf(x);
        }
        dsum += w_lane;
        int m = cnt - base; if (m > 32) m = 32;
        int nsteps = (m + 1) >> 1;
        #pragma unroll 4
        for (int j = 0; j < nsteps; j++) {
            int src = 2 * j + half;
            int   c = __shfl_sync(0xFFFFFFFFu, c_lane, src);
            float w = __shfl_sync(0xFFFFFFFFu, w_lane, src);
            uint2 raw = __ldg(&Wh4[(size_t)c * 16 + hl]);
            float2 v0 = __half22float2(*(const __half2*)&raw.x);
            float2 v1 = __half22float2(*(const __half2*)&raw.y);
            acc.x = fmaf(w, v0.x, acc.x);
            acc.y = fmaf(w, v0.y, acc.y);
            acc.z = fmaf(w, v1.x, acc.z);
            acc.w = fmaf(w, v1.y, acc.w);
        }
    }

    #pragma unroll
    for (int o = 16; o > 0; o >>= 1)
        dsum += __shfl_xor_sync(0xFFFFFFFFu, dsum, o);
    const float inv = 1.f / (dsum + 1e-10f);

    acc.x += __shfl_xor_sync(0xFFFFFFFFu, acc.x, 16);
    acc.y += __shfl_xor_sync(0xFFFFFFFFu, acc.y, 16);
    acc.z += __shfl_xor_sync(0xFFFFFFFFu, acc.z, 16);
    acc.w += __shfl_xor_sync(0xFFFFFFFFu, acc.w, 16);

    if (half == 0) {
        acc.x *= inv; acc.y *= inv; acc.z *= inv; acc.w *= inv;
        ((float4*)out)[(size_t)warp * 16 + hl] = acc;
    }

    if (lane == 0) g_count[warp] = 0;   // self-clean for next replay
}

// ---------------------------------------------------------------------------
extern "C" void kernel_launch(void* const* d_in, const int* in_sizes, int n_in,
                              void* d_out, int out_size) {
    const float* h   = (const float*)d_in[0];
    const int*   row = (const int*)d_in[1];
    const int*   col = (const int*)d_in[2];
    const float* W   = (const float*)d_in[3];
    const float* a   = (const float*)d_in[4];
    float*       out = (float*)d_out;

    gemm_hist_kernel<<<TOTAL_BLOCKS, 256>>>(h, W, a, row);
    scan1_kernel<<<SCAN_NB, SCAN_B>>>();
    scan3_kernel<<<SCAN_NB, SCAN_B>>>();
    scatter_kernel<<<(N_EDGES / 4 + 255) / 256, 256>>>(row, col);
    agg_csr_kernel<<<(N_NODES * 32 + 255) / 256, 256>>>(out);
}